// round 5
// baseline (speedup 1.0000x reference)
#include <cuda_runtime.h>
#include <cuda_bf16.h>

// Problem constants
#define BB 2
#define SS 2048
#define EE 1024
#define HH 16
#define DD 64
#define ROWS (BB * SS)        // 4096
#define QKV_N (3 * EE)        // 3072

// Scratch (device globals — no allocation allowed). Kernels reference these
// directly so kernel_launch contains ONLY kernel launches (max capture safety).
__device__ float g_qkv[ROWS * QKV_N];   // [4096, 3072]  (q | k | v per row)
__device__ float g_attn[ROWS * EE];     // [4096, 1024]  attention output

// ---------------------------------------------------------------------------
// SGEMM core: C[M,N] = A[M,K] @ B[K,N] + bias[N]
// BM=BN=128, BK=16, 256 threads, 8x8 per thread. M%128==0, N%128==0, K%16==0.
// ---------------------------------------------------------------------------
__device__ __forceinline__ void sgemm_body(
    int M, int N, int K,
    const float* __restrict__ A, const float* __restrict__ B,
    const float* __restrict__ bias, float* __restrict__ C)
{
    __shared__ float As[16][128];
    __shared__ float Bs[16][128];

    const int tid = threadIdx.x;
    const int bm = blockIdx.y * 128;
    const int bn = blockIdx.x * 128;
    const int tx = tid & 15;          // n direction
    const int ty = tid >> 4;          // m direction

    float acc[8][8];
#pragma unroll
    for (int i = 0; i < 8; i++)
#pragma unroll
        for (int j = 0; j < 8; j++) acc[i][j] = 0.0f;

    for (int k0 = 0; k0 < K; k0 += 16) {
#pragma unroll
        for (int i = 0; i < 2; i++) {
            int slot = i * 256 + tid;           // [0, 512)
            int r  = slot >> 2;                 // A row within tile
            int c4 = slot & 3;                  // float4 index within 16 cols
            float4 a = *(const float4*)&A[(size_t)(bm + r) * K + k0 + c4 * 4];
            As[c4 * 4 + 0][r] = a.x;
            As[c4 * 4 + 1][r] = a.y;
            As[c4 * 4 + 2][r] = a.z;
            As[c4 * 4 + 3][r] = a.w;
            int br  = slot >> 5;                // [0,16)
            int bc4 = slot & 31;                // [0,32)
            float4 bv = *(const float4*)&B[(size_t)(k0 + br) * N + bn + bc4 * 4];
            *(float4*)&Bs[br][bc4 * 4] = bv;
        }
        __syncthreads();

#pragma unroll
        for (int kk = 0; kk < 16; kk++) {
            float ra[8], rb[8];
            *(float4*)&ra[0] = *(const float4*)&As[kk][ty * 8];
            *(float4*)&ra[4] = *(const float4*)&As[kk][ty * 8 + 4];
            *(float4*)&rb[0] = *(const float4*)&Bs[kk][tx * 8];
            *(float4*)&rb[4] = *(const float4*)&Bs[kk][tx * 8 + 4];
#pragma unroll
            for (int i = 0; i < 8; i++)
#pragma unroll
                for (int j = 0; j < 8; j++)
                    acc[i][j] += ra[i] * rb[j];
        }
        __syncthreads();
    }

#pragma unroll
    for (int i = 0; i < 8; i++) {
        int row = bm + ty * 8 + i;
        float* Crow = &C[(size_t)row * N + bn];
#pragma unroll
        for (int j = 0; j < 8; j += 4) {
            float4 o;
            int n = tx * 8 + j;
            o.x = acc[i][j + 0] + bias[bn + n + 0];
            o.y = acc[i][j + 1] + bias[bn + n + 1];
            o.z = acc[i][j + 2] + bias[bn + n + 2];
            o.w = acc[i][j + 3] + bias[bn + n + 3];
            *(float4*)&Crow[n] = o;
        }
    }
}

// GEMM 1: g_qkv = x @ Wqkv + bqkv   [4096,1024]@[1024,3072]
__global__ __launch_bounds__(256, 2) void qkv_gemm(
    const float* __restrict__ x, const float* __restrict__ Wqkv,
    const float* __restrict__ bqkv)
{
    sgemm_body(ROWS, QKV_N, EE, x, Wqkv, bqkv, g_qkv);
}

// GEMM 2: out = g_attn @ Wout + bout   [4096,1024]@[1024,1024]
__global__ __launch_bounds__(256, 2) void out_gemm(
    const float* __restrict__ Wout, const float* __restrict__ bout,
    float* __restrict__ out)
{
    sgemm_body(ROWS, EE, EE, g_attn, Wout, bout, out);
}

// ---------------------------------------------------------------------------
// Flash attention (fp32 SIMT): grid (S/128 qtiles, B*H), 128 threads.
// Thread t owns query row qtile*128+t: q (64 regs) and O (64 regs) in regs.
// K/V tiles of 64 rows staged in shared, read as warp broadcasts.
// ---------------------------------------------------------------------------
__global__ __launch_bounds__(128) void flash_attn(const int* __restrict__ mask)
{
    __shared__ float Ks[64][64];
    __shared__ float Vs[64][64];
    __shared__ float msk[64];

    const int t  = threadIdx.x;
    const int b  = blockIdx.y / HH;
    const int h  = blockIdx.y % HH;
    const int qi = blockIdx.x * 128 + t;

    // Load q row, pre-scaled by 1/sqrt(D) = 0.125
    float4 q4[16];
    {
        const float4* qsrc =
            (const float4*)&g_qkv[(size_t)(b * SS + qi) * QKV_N + h * DD];
#pragma unroll
        for (int i = 0; i < 16; i++) {
            float4 v = qsrc[i];
            v.x *= 0.125f; v.y *= 0.125f; v.z *= 0.125f; v.w *= 0.125f;
            q4[i] = v;
        }
    }

    float4 O4[16];
#pragma unroll
    for (int i = 0; i < 16; i++) O4[i] = make_float4(0.f, 0.f, 0.f, 0.f);
    float m = -1e30f;
    float l = 0.0f;

    for (int kt = 0; kt < SS / 64; kt++) {
        // Cooperative load of K and V tiles (64 rows x 64 cols each)
#pragma unroll
        for (int i = 0; i < 8; i++) {
            int slot = i * 128 + t;            // [0, 1024) float4 slots
            int rr = slot >> 4;                // row in tile
            int c4 = slot & 15;                // float4 col
            size_t base = (size_t)(b * SS + kt * 64 + rr) * QKV_N + h * DD;
            ((float4*)&Ks[rr][0])[c4] = *(const float4*)&g_qkv[base + EE + c4 * 4];
            ((float4*)&Vs[rr][0])[c4] = *(const float4*)&g_qkv[base + 2 * EE + c4 * 4];
        }
        if (t < 64)
            msk[t] = (mask[b * SS + kt * 64 + t] == 0) ? -1e30f : 0.0f;
        __syncthreads();

        for (int kk = 0; kk < 64; kk++) {
            const float4* Krow = (const float4*)&Ks[kk][0];
            float a0 = 0.f, a1 = 0.f, a2 = 0.f, a3 = 0.f;
#pragma unroll
            for (int i = 0; i < 16; i++) {
                float4 kv = Krow[i];
                a0 += q4[i].x * kv.x;
                a1 += q4[i].y * kv.y;
                a2 += q4[i].z * kv.z;
                a3 += q4[i].w * kv.w;
            }
            float s = (a0 + a1) + (a2 + a3) + msk[kk];

            const float4* Vrow = (const float4*)&Vs[kk][0];
            if (s <= m) {
                // common path: no new running max
                float p = __expf(s - m);
                l += p;
#pragma unroll
                for (int i = 0; i < 16; i++) {
                    float4 vv = Vrow[i];
                    O4[i].x += p * vv.x;
                    O4[i].y += p * vv.y;
                    O4[i].z += p * vv.z;
                    O4[i].w += p * vv.w;
                }
            } else {
                // rare path: rescale (p == 1 at the new max)
                float alpha = __expf(m - s);
                m = s;
                l = l * alpha + 1.0f;
#pragma unroll
                for (int i = 0; i < 16; i++) {
                    float4 vv = Vrow[i];
                    O4[i].x = O4[i].x * alpha + vv.x;
                    O4[i].y = O4[i].y * alpha + vv.y;
                    O4[i].z = O4[i].z * alpha + vv.z;
                    O4[i].w = O4[i].w * alpha + vv.w;
                }
            }
        }
        __syncthreads();
    }

    float inv = 1.0f / l;
    float4* dst = (float4*)&g_attn[(size_t)(b * SS + qi) * EE + h * DD];
#pragma unroll
    for (int i = 0; i < 16; i++) {
        float4 o = O4[i];
        o.x *= inv; o.y *= inv; o.z *= inv; o.w *= inv;
        dst[i] = o;
    }
}

// ---------------------------------------------------------------------------
// Launch — pure kernel launches only (graph-capture safe).
// inputs: x[B,S,E] f32, mask[B,S] i32, Wqkv[E,3E] f32, bqkv[3E] f32,
//         Wout[E,E] f32, bout[E] f32. output: [B,S,E] f32.
// ---------------------------------------------------------------------------
extern "C" void kernel_launch(void* const* d_in, const int* in_sizes, int n_in,
                              void* d_out, int out_size)
{
    const float* x    = (const float*)d_in[0];
    const int*   mask = (const int*)d_in[1];
    const float* Wqkv = (const float*)d_in[2];
    const float* bqkv = (const float*)d_in[3];
    const float* Wout = (const float*)d_in[4];
    const float* bout = (const float*)d_in[5];
    float* out = (float*)d_out;

    {   // 1) qkv = x @ Wqkv + bqkv
        dim3 grid(QKV_N / 128, ROWS / 128);
        qkv_gemm<<<grid, 256>>>(x, Wqkv, bqkv);
    }
    {   // 2) attention -> g_attn
        dim3 grid(SS / 128, BB * HH);
        flash_attn<<<grid, 128>>>(mask);
    }
    {   // 3) out = g_attn @ Wout + bout
        dim3 grid(EE / 128, ROWS / 128);
        out_gemm<<<grid, 256>>>(Wout, bout, out);
    }
}